// round 10
// baseline (speedup 1.0000x reference)
#include <cuda_runtime.h>
#include <math.h>
#include <stdint.h>

#define B_   8
#define S_   4096
#define H_   1024
#define R_   (B_ * H_)
#define CAP  128
#define TAU_LG2   4.76107544f     /* 3.3 / ln2 */
#define INV_LN2   1.44269504f

// ---------------- device scratch (zero-initialized at load; select restores) ----------------
__device__ float2 g_buf[R_ * CAP];   // survivor (score, value) per row
__device__ int    g_cnt[R_];
__device__ float  g_pooled[R_];

__device__ __forceinline__ float neg_inf() { return __int_as_float(0xff800000); }

__device__ __forceinline__ uint32_t smem_u32(const void* p) {
    uint32_t a;
    asm("{ .reg .u64 t; cvta.to.shared.u64 t, %1; cvt.u32.u64 %0, t; }" : "=r"(a) : "l"(p));
    return a;
}

__device__ __forceinline__ void flt_test(float x, float g, int r) {
    float sc = fmaf(g, INV_LN2, __log2f(x));  // NaN (x<0) / -inf (x==0): never > TAU
    if (sc > TAU_LG2) {
        int p = atomicAdd(&g_cnt[r], 1);
        if (p < CAP) g_buf[r * CAP + p] = make_float2(sc, x);
    }
}

// ---------------- 1: streaming filter — ALL global loads via cp.async ----------------
// Tile: 32 h x 256 s per block (256 thr, 64 KB dyn smem).
// Both streams loaded with cp.async.cg 16B (LDGSTS: no outstanding-miss cap on
// the LDG queue) -> 64 KB in flight per block before a single wait.
//   hidden -> sh_h[s][h]          (compute read: bank = lane, conflict-free)
//   gumbel -> sh_g4[h][col ^ h]   (16B-chunk XOR swizzle: conflict-free LDS.128)
__global__ __launch_bounds__(256) void k_filter(const float* __restrict__ hidden,
                                                const float* __restrict__ gumbel) {
    extern __shared__ float smem_dyn[];
    float*  sh_h  = smem_dyn;                      // 32 KB: [256 s][32 h]
    float4* sh_g4 = (float4*)(smem_dyn + 8192);    // 32 KB: [32 h][64 chunks swizzled]

    int blk  = blockIdx.x;                   // 0..4095
    int sblk = blk & 15;                     // 16 s-blocks of 256
    int hblk = (blk >> 4) & 31;              // 32 h-blocks of 32
    int b    = blk >> 9;                     // 8 batches
    int s0   = sblk * 256;
    int h0   = hblk * 32;
    int tid  = threadIdx.x;

    uint32_t sh_h_a  = smem_u32(sh_h);
    uint32_t sh_g_a  = smem_u32(sh_g4);

    // ---- issue hidden: 2048 x 16B chunks (8 per thread), 128B-line exact ----
#pragma unroll
    for (int k = 0; k < 8; ++k) {
        int c   = tid + k * 256;
        int s   = c >> 3;                    // 8 chunks per 128B s-row
        int off = c & 7;
        const float* src = hidden + ((size_t)(b * S_ + s0 + s)) * H_ + h0 + off * 4;
        uint32_t dst = sh_h_a + (uint32_t)(s * 128 + off * 16);
        asm volatile("cp.async.cg.shared.global [%0], [%1], 16;" :: "r"(dst), "l"(src));
    }
    // ---- issue gumbel: 2048 x 16B chunks (8 per thread), swizzled dst ----
#pragma unroll
    for (int k = 0; k < 8; ++k) {
        int c   = tid + k * 256;
        int h   = c >> 6;                    // 64 chunks per 1KB gumbel row
        int col = c & 63;
        const float* src = gumbel + ((size_t)(b * H_ + h0 + h)) * S_ + s0 + col * 4;
        uint32_t dst = sh_g_a + (uint32_t)((h * 64 + (col ^ h)) * 16);
        asm volatile("cp.async.cg.shared.global [%0], [%1], 16;" :: "r"(dst), "l"(src));
    }
    asm volatile("cp.async.commit_group;" ::: "memory");
    asm volatile("cp.async.wait_group 0;" ::: "memory");
    __syncthreads();

    // ---- compute: warp w covers s in [w*32, w*32+32), lane = h ----
    int w    = tid >> 5;
    int lane = tid & 31;
    int r    = b * H_ + h0 + lane;

#pragma unroll
    for (int q = 0; q < 8; ++q) {
        int s4 = w * 8 + q;                  // s-quad index (s = 4*s4)
        float4 g4 = sh_g4[lane * 64 + (s4 ^ lane)];
        int sb = s4 * 4;
        float x0 = sh_h[(sb + 0) * 32 + lane];
        float x1 = sh_h[(sb + 1) * 32 + lane];
        float x2 = sh_h[(sb + 2) * 32 + lane];
        float x3 = sh_h[(sb + 3) * 32 + lane];
        flt_test(x0, g4.x, r);
        flt_test(x1, g4.y, r);
        flt_test(x2, g4.z, r);
        flt_test(x3, g4.w, r);
    }
}

// ---------------- 2: per-row top-8 over survivors (+ inline exact fallback) ----------------
__global__ __launch_bounds__(256) void k_select(const float* __restrict__ hidden,
                                                const float* __restrict__ gumbel) {
    int row  = (blockIdx.x * blockDim.x + threadIdx.x) >> 5;
    int lane = threadIdx.x & 31;
    if (row >= R_) return;

    const float NI = neg_inf();
    int cnt = g_cnt[row];
    if (lane == 0) g_cnt[row] = 0;           // restore for next graph replay

    float sum = 0.f;

    if (cnt >= 8 && cnt <= CAP) {
        float sc0 = NI, sc1 = NI, sc2 = NI, sc3 = NI;
        float v0 = 0.f, v1 = 0.f, v2 = 0.f, v3 = 0.f;
        int base = row * CAP;
        if (lane      < cnt) { float2 c = g_buf[base + lane];      sc0 = c.x; v0 = c.y; }
        if (lane + 32 < cnt) { float2 c = g_buf[base + lane + 32]; sc1 = c.x; v1 = c.y; }
        if (lane + 64 < cnt) { float2 c = g_buf[base + lane + 64]; sc2 = c.x; v2 = c.y; }
        if (lane + 96 < cnt) { float2 c = g_buf[base + lane + 96]; sc3 = c.x; v3 = c.y; }

        for (int round = 0; round < 8; ++round) {
            float bs = sc0, bv = v0; int bi = 0;
            if (sc1 > bs) { bs = sc1; bv = v1; bi = 1; }
            if (sc2 > bs) { bs = sc2; bv = v2; bi = 2; }
            if (sc3 > bs) { bs = sc3; bv = v3; bi = 3; }
            float m = bs;
#pragma unroll
            for (int off = 16; off > 0; off >>= 1)
                m = fmaxf(m, __shfl_xor_sync(0xffffffffu, m, off));
            unsigned ball = __ballot_sync(0xffffffffu, bs == m);
            int src = __ffs(ball) - 1;
            sum += __shfl_sync(0xffffffffu, bv, src);
            if (lane == src) {
                if      (bi == 0) sc0 = NI;
                else if (bi == 1) sc1 = NI;
                else if (bi == 2) sc2 = NI;
                else              sc3 = NI;
            }
        }
    } else {
        // exact fallback (rare; expected never): warp rescans the full row
        int b = row >> 10;
        int h = row & (H_ - 1);
        const float* hp = hidden + (size_t)b * S_ * H_ + h;
        const float* gp = gumbel + (size_t)row * S_;

        float lsc[8], lv[8];
#pragma unroll
        for (int j = 0; j < 8; ++j) { lsc[j] = NI; lv[j] = 0.f; }

        for (int s = lane; s < S_; s += 32) {
            float x = hp[(size_t)s * H_];
            float g = gp[s];
            float sc = (x > 0.f) ? fmaf(g, INV_LN2, __log2f(x)) : NI;
            if (sc > lsc[7]) {
                lsc[7] = sc; lv[7] = x;
#pragma unroll
                for (int j = 7; j > 0; --j) {
                    if (lsc[j] > lsc[j - 1]) {
                        float ts = lsc[j]; lsc[j] = lsc[j - 1]; lsc[j - 1] = ts;
                        float tv = lv[j];  lv[j]  = lv[j - 1];  lv[j - 1]  = tv;
                    }
                }
            }
        }
        int ptr = 0;
        for (int round = 0; round < 8; ++round) {
            float cand = NI, cval = 0.f;
#pragma unroll
            for (int j = 0; j < 8; ++j)
                if (j == ptr) { cand = lsc[j]; cval = lv[j]; }
            float m = cand;
#pragma unroll
            for (int off = 16; off > 0; off >>= 1)
                m = fmaxf(m, __shfl_xor_sync(0xffffffffu, m, off));
            unsigned ball = __ballot_sync(0xffffffffu, (cand == m) && (ptr < 8));
            if (ball == 0u) continue;        // remaining are -inf: contributes 0 (matches ref)
            int src = __ffs(ball) - 1;
            sum += __shfl_sync(0xffffffffu, cval, src);
            if (lane == src) ptr++;
        }
    }

    if (lane == 0) g_pooled[row] = sum;
}

// ---------------- 3: out = tanh(pooled @ W^T + bias) ----------------
__global__ __launch_bounds__(256) void k_gemm(const float* __restrict__ W,
                                              const float* __restrict__ bias,
                                              float* __restrict__ out) {
    int j = blockIdx.x;
    float acc[8];
#pragma unroll
    for (int bb = 0; bb < 8; ++bb) acc[bb] = 0.f;

    for (int h = threadIdx.x; h < H_; h += 256) {
        float wv = W[(size_t)j * H_ + h];
#pragma unroll
        for (int bb = 0; bb < 8; ++bb)
            acc[bb] += g_pooled[bb * H_ + h] * wv;
    }
#pragma unroll
    for (int bb = 0; bb < 8; ++bb)
#pragma unroll
        for (int off = 16; off > 0; off >>= 1)
            acc[bb] += __shfl_xor_sync(0xffffffffu, acc[bb], off);

    __shared__ float tot[8];
    if (threadIdx.x < 8) tot[threadIdx.x] = 0.f;
    __syncthreads();
    if ((threadIdx.x & 31) == 0) {
#pragma unroll
        for (int bb = 0; bb < 8; ++bb) atomicAdd(&tot[bb], acc[bb]);
    }
    __syncthreads();
    if (threadIdx.x < 8)
        out[threadIdx.x * H_ + j] = tanhf(tot[threadIdx.x] + bias[j]);
}

// ---------------- launch ----------------
extern "C" void kernel_launch(void* const* d_in, const int* in_sizes, int n_in,
                              void* d_out, int out_size) {
    const float* hidden = (const float*)d_in[0];
    const float* gumbel = (const float*)d_in[1];
    const float* W      = (const float*)d_in[2];
    const float* bias   = (const float*)d_in[3];
    float*       out    = (float*)d_out;
    (void)in_sizes; (void)n_in; (void)out_size;

    const int FILTER_SMEM = 64 * 1024;
    static int attr_done = 0;
    if (!attr_done) {
        cudaFuncSetAttribute(k_filter, cudaFuncAttributeMaxDynamicSharedMemorySize, FILTER_SMEM);
        attr_done = 1;
    }

    k_filter<<<4096, 256, FILTER_SMEM>>>(hidden, gumbel);
    k_select<<<1024, 256>>>(hidden, gumbel);
    k_gemm  <<<1024, 256>>>(W, bias, out);
}